// round 9
// baseline (speedup 1.0000x reference)
#include <cuda_runtime.h>
#include <cuda_bf16.h>
#include <cstdint>

// Problem constants
#define HWX   65536          // 256*256
#define NPIX  131072ul       // 2*256*256
#define CCH   320
#define SPL   160

// Scratch (static __device__ — no allocations allowed)
__device__ float g_mean[131072];
__device__ float g_rstd[131072];
__device__ __nv_bfloat16 g_wa_hi[1024 * 320];   // combined weights, bf16 hi (rows 960..1023 zero)
__device__ __nv_bfloat16 g_wa_lo[1024 * 320];   // combined weights, bf16 lo residual
__device__ float g_bc[1024];                    // combined biases (padded, rows>=960 zero)
__device__ float g_qkv[960ul * 131072ul];   // GEMM output: rows 0..479 = h(q,k,v), 480..959 = v(q,k,v)
__device__ float g_qkvT[480ul * 131072ul];  // vertical qkv, H-major
__device__ float g_avs[160ul * 131072ul];   // vertical attn out, [c][b][w][h]

// byte-offset swizzle for 128B-stride rows: XOR bits[4:6] with (row&7)
#define SWZ128(o) ((o) ^ (((o) >> 3) & 0x70))

// ---------------------------------------------------------------------------
// mma.sync m16n8k16 bf16 (base sm_103 — NOT arch-gated like tcgen05)
// ---------------------------------------------------------------------------
__device__ __forceinline__ void mma_bf16(float* c, const uint32_t* a, const uint32_t* b) {
    asm volatile(
        "mma.sync.aligned.m16n8k16.row.col.f32.bf16.bf16.f32 "
        "{%0,%1,%2,%3}, {%4,%5,%6,%7}, {%8,%9}, {%0,%1,%2,%3};"
        : "+f"(c[0]), "+f"(c[1]), "+f"(c[2]), "+f"(c[3])
        : "r"(a[0]), "r"(a[1]), "r"(a[2]), "r"(a[3]), "r"(b[0]), "r"(b[1]));
}

// packed fp32x2 FMA (sm_103 FFMA2)
__device__ __forceinline__ float2 ffma2(float2 a, float2 b, float2 c) {
    float2 d;
    asm("{ .reg .b64 ra, rb, rc, rd;\n\t"
        "mov.b64 ra, {%2, %3}; mov.b64 rb, {%4, %5}; mov.b64 rc, {%6, %7};\n\t"
        "fma.rn.f32x2 rd, ra, rb, rc;\n\t"
        "mov.b64 {%0, %1}, rd; }"
        : "=f"(d.x), "=f"(d.y)
        : "f"(a.x), "f"(a.y), "f"(b.x), "f"(b.y), "f"(c.x), "f"(c.y));
    return d;
}

// ---------------------------------------------------------------------------
// 1) Per-pixel LayerNorm stats over channels
// ---------------------------------------------------------------------------
__global__ void ln_stats_kernel(const float* __restrict__ x) {
    int p  = blockIdx.x * 256 + threadIdx.x;
    int b  = p >> 16;
    int hw = p & 65535;
    const float* xp = x + (size_t)b * CCH * HWX + hw;
    float s = 0.f, s2 = 0.f;
#pragma unroll 4
    for (int c = 0; c < CCH; c++) {
        float v = __ldg(xp + (size_t)c * HWX);
        s += v; s2 += v * v;
    }
    float mu  = s * (1.f / 320.f);
    float var = s2 * (1.f / 320.f) - mu * mu;
    g_mean[p] = mu;
    g_rstd[p] = rsqrtf(var + 1e-5f);
}

// ---------------------------------------------------------------------------
// 2) Fold conv into QKV, output bf16 hi/lo split. Rows 960..1023 zero-padded.
// ---------------------------------------------------------------------------
__global__ void combine_w_kernel(
    const float* __restrict__ conv_w, const float* __restrict__ conv_b,
    const float* w0, const float* b0, const float* w1, const float* b1,
    const float* w2, const float* b2, const float* w3, const float* b3,
    const float* w4, const float* b4, const float* w5, const float* b5)
{
    int r = blockIdx.x;            // 0..1023
    int c = threadIdx.x;           // 0..319
    if (r >= 960) {
        g_wa_hi[r * 320 + c] = __float2bfloat16(0.f);
        g_wa_lo[r * 320 + c] = __float2bfloat16(0.f);
        if (c == 0) g_bc[r] = 0.f;
        return;
    }
    int g = r / 160, ro = r % 160;
    const float* wg; const float* bg;
    switch (g) {
        case 0: wg = w0; bg = b0; break;
        case 1: wg = w1; bg = b1; break;
        case 2: wg = w2; bg = b2; break;
        case 3: wg = w3; bg = b3; break;
        case 4: wg = w4; bg = b4; break;
        default: wg = w5; bg = b5; break;
    }
    int half = (g >= 3) ? 1 : 0;
    __shared__ float wrow[160];
    if (threadIdx.x < 160) wrow[threadIdx.x] = __ldg(wg + ro * 160 + threadIdx.x);
    __syncthreads();
    const float* cw = conv_w + (size_t)half * 160 * 320 + c;
    float s = 0.f;
#pragma unroll 4
    for (int d = 0; d < 160; d++)
        s += wrow[d] * __ldg(cw + d * 320);
    __nv_bfloat16 hi = __float2bfloat16(s);
    g_wa_hi[r * 320 + c] = hi;
    g_wa_lo[r * 320 + c] = __float2bfloat16(s - __bfloat162float(hi));
    if (c == 0) {
        float sb = __ldg(bg + ro);
        const float* cb = conv_b + half * 160;
        for (int d = 0; d < 160; d++) sb += wrow[d] * __ldg(cb + d);
        g_bc[r] = sb;
    }
}

// ---------------------------------------------------------------------------
// 3) HMMA GEMM: qkv[960][131072] = Wc @ LN(x) + bc
//    CTA tile M=128 x N=128, K chunks of 64. bf16 Markidis 3-term split.
//    8 warps = 4(m) x 2(n); warp tile 32x64; mma.sync m16n8k16.
//    Smem tiles (dynamic, 64KB): Ah[128][64], Al, Bh[128 n][64 k], Bl —
//    all 128B row stride with SWZ128 (conflict-free frag loads).
// ---------------------------------------------------------------------------
#define SM_AHI 0
#define SM_ALO 16384
#define SM_BHI 32768
#define SM_BLO 49152
#define GEMM_SMEM 65536

__global__ void __launch_bounds__(256, 1) gemm_tc_kernel(
    const float* __restrict__ x,
    const float* __restrict__ lnw, const float* __restrict__ lnb)
{
    extern __shared__ char smem[];
    int tid = threadIdx.x;
    int wid = tid >> 5, lid = tid & 31;
    int m0  = blockIdx.x * 128;        // 0..896 (rows >=960 are zero pad)
    int n0  = blockIdx.y * 128;

    // B-tile source (all 128 columns of a block live in one batch image)
    int b = n0 >> 16;
    const float* xb = x + (size_t)b * CCH * HWX + (n0 & 65535);
    int tn = tid & 127;            // column (pixel) within tile
    int th = tid >> 7;             // 0/1: which half of the kk range
    float meanv = g_mean[n0 + tn];
    float rstdv = g_rstd[n0 + tn];

    const uint32_t* wh = (const uint32_t*)g_wa_hi;
    const uint32_t* wl = (const uint32_t*)g_wa_lo;

    // fragment coordinates
    int fg = lid >> 2;             // 0..7  (group/row id)
    int ft = lid & 3;              // 0..3
    int wm = (wid & 3) * 32;       // warp m offset in tile
    int wn = (wid >> 2) * 64;      // warp n offset in tile

    float acc[2][8][4];
#pragma unroll
    for (int mi = 0; mi < 2; mi++)
#pragma unroll
        for (int ni = 0; ni < 8; ni++)
#pragma unroll
            for (int q = 0; q < 4; q++) acc[mi][ni][q] = 0.f;

    for (int c = 0; c < 5; c++) {
        int k0 = c * 64;
        // stage A: 128 rows x 64 bf16 (hi + lo) — 4096 u32 each, 16 per thread
#pragma unroll
        for (int i = 0; i < 16; i++) {
            int idx = i * 256 + tid;
            int m = idx >> 5, j = idx & 31;            // j = k-pair index
            uint32_t go  = (uint32_t)((m0 + m) * 320 + k0) / 2 + j;
            uint32_t off = SWZ128((uint32_t)(m * 128 + j * 4));
            *(uint32_t*)(smem + SM_AHI + off) = __ldg(wh + go);
            *(uint32_t*)(smem + SM_ALO + off) = __ldg(wl + go);
        }
        // stage B: [n][k] tile 128 x 64 bf16, LN applied, hi/lo split
#pragma unroll
        for (int u = 0; u < 16; u++) {
            int kk = (th * 16 + u) * 2;
            int k  = k0 + kk;
            float lw0 = __ldg(lnw + k), lw1 = __ldg(lnw + k + 1);
            float lb0 = __ldg(lnb + k), lb1 = __ldg(lnb + k + 1);
            float v0 = fmaf((__ldg(xb + (size_t)k * HWX + tn) - meanv) * rstdv, lw0, lb0);
            float v1 = fmaf((__ldg(xb + (size_t)(k + 1) * HWX + tn) - meanv) * rstdv, lw1, lb1);
            __nv_bfloat162 h2 = __floats2bfloat162_rn(v0, v1);
            __nv_bfloat162 l2 = __floats2bfloat162_rn(v0 - __bfloat162float(h2.x),
                                                      v1 - __bfloat162float(h2.y));
            uint32_t off = SWZ128((uint32_t)(tn * 128 + kk * 2));
            *(uint32_t*)(smem + SM_BHI + off) = *(uint32_t*)&h2;
            *(uint32_t*)(smem + SM_BLO + off) = *(uint32_t*)&l2;
        }
        __syncthreads();

#pragma unroll
        for (int s = 0; s < 4; s++) {           // k16 steps within the 64 chunk
            int kb = s * 32;                    // byte offset of this k16 (16 bf16)
            // A fragments (hi & lo) for both m16 tiles
            uint32_t ah[2][4], al[2][4];
#pragma unroll
            for (int mi = 0; mi < 2; mi++) {
                int r0 = wm + mi * 16 + fg;
                int r1 = r0 + 8;
                uint32_t o0 = SWZ128((uint32_t)(r0 * 128 + kb + ft * 4));
                uint32_t o1 = SWZ128((uint32_t)(r1 * 128 + kb + ft * 4));
                uint32_t o2 = SWZ128((uint32_t)(r0 * 128 + kb + ft * 4 + 16));
                uint32_t o3 = SWZ128((uint32_t)(r1 * 128 + kb + ft * 4 + 16));
                ah[mi][0] = *(const uint32_t*)(smem + SM_AHI + o0);
                ah[mi][1] = *(const uint32_t*)(smem + SM_AHI + o1);
                ah[mi][2] = *(const uint32_t*)(smem + SM_AHI + o2);
                ah[mi][3] = *(const uint32_t*)(smem + SM_AHI + o3);
                al[mi][0] = *(const uint32_t*)(smem + SM_ALO + o0);
                al[mi][1] = *(const uint32_t*)(smem + SM_ALO + o1);
                al[mi][2] = *(const uint32_t*)(smem + SM_ALO + o2);
                al[mi][3] = *(const uint32_t*)(smem + SM_ALO + o3);
            }
            // B fragments + MMAs per n8 tile
#pragma unroll
            for (int ni = 0; ni < 8; ni++) {
                int nr = wn + ni * 8 + fg;
                uint32_t p0 = SWZ128((uint32_t)(nr * 128 + kb + ft * 4));
                uint32_t p1 = SWZ128((uint32_t)(nr * 128 + kb + ft * 4 + 16));
                uint32_t bh[2], bl[2];
                bh[0] = *(const uint32_t*)(smem + SM_BHI + p0);
                bh[1] = *(const uint32_t*)(smem + SM_BHI + p1);
                bl[0] = *(const uint32_t*)(smem + SM_BLO + p0);
                bl[1] = *(const uint32_t*)(smem + SM_BLO + p1);
#pragma unroll
                for (int mi = 0; mi < 2; mi++) {
                    mma_bf16(acc[mi][ni], ah[mi], bh);
                    mma_bf16(acc[mi][ni], ah[mi], bl);
                    mma_bf16(acc[mi][ni], al[mi], bh);
                }
            }
        }
        __syncthreads();
    }

    // epilogue: c0,c1 -> (row, t*2 / t*2+1); c2,c3 -> (row+8, ...)
#pragma unroll
    for (int mi = 0; mi < 2; mi++) {
        int r0 = m0 + wm + mi * 16 + fg;
        int r1 = r0 + 8;
        float bias0 = (r0 < 960) ? g_bc[r0] : 0.f;
        float bias1 = (r1 < 960) ? g_bc[r1] : 0.f;
#pragma unroll
        for (int ni = 0; ni < 8; ni++) {
            int nc = n0 + wn + ni * 8 + ft * 2;
            if (r0 < 960) {
                float2 o = make_float2(acc[mi][ni][0] + bias0, acc[mi][ni][1] + bias0);
                *(float2*)&g_qkv[(size_t)r0 * NPIX + nc] = o;
            }
            if (r1 < 960) {
                float2 o = make_float2(acc[mi][ni][2] + bias1, acc[mi][ni][3] + bias1);
                *(float2*)&g_qkv[(size_t)r1 * NPIX + nc] = o;
            }
        }
    }
}

// ---------------------------------------------------------------------------
// 4) Transpose vertical qkv rows (960 matrices of 256x256) into H-major order
// ---------------------------------------------------------------------------
__global__ void transpose_qkv_kernel() {
    __shared__ float tile[32][33];
    int m = blockIdx.z;
    const float* s = g_qkv + 480ul * NPIX + (size_t)m * HWX;
    float* d       = g_qkvT + (size_t)m * HWX;
    int x0 = blockIdx.x * 32, y0 = blockIdx.y * 32;
    int tx = threadIdx.x, ty = threadIdx.y;
#pragma unroll
    for (int i = 0; i < 4; i++)
        tile[ty + i * 8][tx] = s[(size_t)(y0 + ty + i * 8) * 256 + x0 + tx];
    __syncthreads();
#pragma unroll
    for (int i = 0; i < 4; i++)
        d[(size_t)(x0 + ty + i * 8) * 256 + y0 + tx] = tile[tx][ty + i * 8];
}

// ---------------------------------------------------------------------------
// 5) Axial attention (unchanged from R6 passing version)
// ---------------------------------------------------------------------------
template <int VMODE>
__global__ void __launch_bounds__(256) attn_kernel(float* __restrict__ out)
{
    __shared__ float Ks[128 * 36];
    __shared__ float Vs[128 * 36];
    int hd  = blockIdx.x;
    int seq = blockIdx.y;
    int t   = threadIdx.x;

    const float* qkv = (VMODE == 0) ? g_qkv : g_qkvT;

    const float* qb = qkv + (size_t)(hd * 32) * NPIX + (size_t)seq * 256 + t;
    const float* kb = qkv + (size_t)(160 + hd * 32) * NPIX + (size_t)seq * 256;
    const float* vb = qkv + (size_t)(320 + hd * 32) * NPIX + (size_t)seq * 256;

    float2 q2[16];
#pragma unroll
    for (int c = 0; c < 16; c++) {
        q2[c].x = __ldg(qb + (size_t)(2 * c) * NPIX);
        q2[c].y = __ldg(qb + (size_t)(2 * c + 1) * NPIX);
    }

    float mx = -1e30f, l = 0.f;
    float2 acc[16];
#pragma unroll
    for (int c = 0; c < 16; c++) acc[c] = make_float2(0.f, 0.f);
    const float scale = 0.17677669529663688f;

    for (int chunk = 0; chunk < 2; chunk++) {
        int j0 = chunk * 128;
        __syncthreads();
#pragma unroll
        for (int i = 0; i < 16; i++) {
            int idx = t + i * 256;
            int pos = idx & 127, c = idx >> 7;
            Ks[pos * 36 + c] = __ldg(kb + (size_t)c * NPIX + j0 + pos);
            Vs[pos * 36 + c] = __ldg(vb + (size_t)c * NPIX + j0 + pos);
        }
        __syncthreads();
        for (int j = 0; j < 128; j++) {
            const float4* k4 = (const float4*)(Ks + j * 36);
            const float4* v4 = (const float4*)(Vs + j * 36);
            float2 d2 = make_float2(0.f, 0.f);
#pragma unroll
            for (int c = 0; c < 8; c++) {
                float4 kv = k4[c];
                d2 = ffma2(q2[2 * c],     make_float2(kv.x, kv.y), d2);
                d2 = ffma2(q2[2 * c + 1], make_float2(kv.z, kv.w), d2);
            }
            float s = (d2.x + d2.y) * scale;
            if (s > mx) {
                float corr = __expf(mx - s);
                mx = s; l *= corr;
#pragma unroll
                for (int c = 0; c < 16; c++) { acc[c].x *= corr; acc[c].y *= corr; }
            }
            float p = __expf(s - mx);
            l += p;
            float2 pp = make_float2(p, p);
#pragma unroll
            for (int c = 0; c < 8; c++) {
                float4 vv = v4[c];
                acc[2 * c]     = ffma2(pp, make_float2(vv.x, vv.y), acc[2 * c]);
                acc[2 * c + 1] = ffma2(pp, make_float2(vv.z, vv.w), acc[2 * c + 1]);
            }
        }
    }
    float rl = 1.f / l;
    if (VMODE == 0) {
        int b = seq >> 8, h = seq & 255;
        float* o = out + (size_t)(b * 160 + hd * 32) * HWX + h * 256 + t;
#pragma unroll
        for (int c = 0; c < 16; c++) {
            o[(size_t)(2 * c) * HWX]     = acc[c].x * rl;
            o[(size_t)(2 * c + 1) * HWX] = acc[c].y * rl;
        }
    } else {
        float* o = g_avs + (size_t)(hd * 32) * NPIX + (size_t)seq * 256 + t;
#pragma unroll
        for (int c = 0; c < 16; c++) {
            o[(size_t)(2 * c) * NPIX]     = acc[c].x * rl;
            o[(size_t)(2 * c + 1) * NPIX] = acc[c].y * rl;
        }
    }
}

// ---------------------------------------------------------------------------
// 6) Final transpose of vertical attention output into d_out batches 2..3
// ---------------------------------------------------------------------------
__global__ void transpose_av_kernel(float* __restrict__ outp) {
    __shared__ float tile[32][33];
    int z = blockIdx.z;
    int b = z / 160, c = z % 160;
    const float* s = g_avs + (size_t)(c * 2 + b) * HWX;
    float* d = outp + 2ul * 160ul * HWX + (size_t)z * HWX;
    int x0 = blockIdx.x * 32, y0 = blockIdx.y * 32;
    int tx = threadIdx.x, ty = threadIdx.y;
#pragma unroll
    for (int i = 0; i < 4; i++)
        tile[ty + i * 8][tx] = s[(size_t)(y0 + ty + i * 8) * 256 + x0 + tx];
    __syncthreads();
#pragma unroll
    for (int i = 0; i < 4; i++)
        d[(size_t)(x0 + ty + i * 8) * 256 + y0 + tx] = tile[tx][ty + i * 8];
}

// ---------------------------------------------------------------------------
extern "C" void kernel_launch(void* const* d_in, const int* in_sizes, int n_in,
                              void* d_out, int out_size)
{
    const float* x      = (const float*)d_in[0];
    const float* lnw    = (const float*)d_in[1];
    const float* lnb    = (const float*)d_in[2];
    const float* conv_w = (const float*)d_in[3];
    const float* conv_b = (const float*)d_in[4];
    float* out = (float*)d_out;

    cudaFuncSetAttribute(gemm_tc_kernel,
                         cudaFuncAttributeMaxDynamicSharedMemorySize, GEMM_SMEM);

    ln_stats_kernel<<<512, 256>>>(x);
    combine_w_kernel<<<1024, 320>>>(conv_w, conv_b,
        (const float*)d_in[5],  (const float*)d_in[6],
        (const float*)d_in[7],  (const float*)d_in[8],
        (const float*)d_in[9],  (const float*)d_in[10],
        (const float*)d_in[11], (const float*)d_in[12],
        (const float*)d_in[13], (const float*)d_in[14],
        (const float*)d_in[15], (const float*)d_in[16]);
    gemm_tc_kernel<<<dim3(8, 1024), 256, GEMM_SMEM>>>(x, lnw, lnb);
    transpose_qkv_kernel<<<dim3(8, 8, 960), dim3(32, 8)>>>();

    attn_kernel<0><<<dim3(5, 512), 256>>>(out);
    attn_kernel<1><<<dim3(5, 512), 256>>>(out);
    transpose_av_kernel<<<dim3(8, 8, 320), dim3(32, 8)>>>(out);
}

// round 11
// speedup vs baseline: 1.4737x; 1.4737x over previous
#include <cuda_runtime.h>
#include <cstdint>

// Problem constants
#define HWX   65536          // 256*256
#define NPIX  131072ul       // 2*256*256
#define CCH   320
#define SPL   160

// Scratch (static __device__ — no allocations allowed)
__device__ float g_mean[131072];
__device__ float g_rstd[131072];
__device__ float g_wcT[320 * 1024];         // combined weights, TRANSPOSED [k][m], cols 960..1023 zero
__device__ float g_bc[1024];                // combined biases (padded, rows>=960 zero)
__device__ float g_qkv[960ul * 131072ul];   // GEMM output: rows 0..479 = h(q,k,v), 480..959 = v(q,k,v)
__device__ float g_qkvT[480ul * 131072ul];  // vertical qkv, H-major
__device__ float g_avs[160ul * 131072ul];   // vertical attn out, [c][b][w][h]

// ---------------------------------------------------------------------------
// packed fp32x2 FMA (sm_103 FFMA2) — 2x fp32 fma throughput
// ---------------------------------------------------------------------------
__device__ __forceinline__ float2 ffma2(float2 a, float2 b, float2 c) {
    float2 d;
    asm("{ .reg .b64 ra, rb, rc, rd;\n\t"
        "mov.b64 ra, {%2, %3}; mov.b64 rb, {%4, %5}; mov.b64 rc, {%6, %7};\n\t"
        "fma.rn.f32x2 rd, ra, rb, rc;\n\t"
        "mov.b64 {%0, %1}, rd; }"
        : "=f"(d.x), "=f"(d.y)
        : "f"(a.x), "f"(a.y), "f"(b.x), "f"(b.y), "f"(c.x), "f"(c.y));
    return d;
}

// ---------------------------------------------------------------------------
// 1) Per-pixel LayerNorm stats over channels
// ---------------------------------------------------------------------------
__global__ void ln_stats_kernel(const float* __restrict__ x) {
    int p  = blockIdx.x * 256 + threadIdx.x;
    int b  = p >> 16;
    int hw = p & 65535;
    const float* xp = x + (size_t)b * CCH * HWX + hw;
    float s = 0.f, s2 = 0.f;
#pragma unroll 4
    for (int c = 0; c < CCH; c++) {
        float v = __ldg(xp + (size_t)c * HWX);
        s += v; s2 += v * v;
    }
    float mu  = s * (1.f / 320.f);
    float var = s2 * (1.f / 320.f) - mu * mu;
    g_mean[p] = mu;
    g_rstd[p] = rsqrtf(var + 1e-5f);
}

// ---------------------------------------------------------------------------
// 2) Fold conv into QKV; store TRANSPOSED fp32 [k][m]. Cols 960..1023 zero.
// ---------------------------------------------------------------------------
__global__ void combine_w_kernel(
    const float* __restrict__ conv_w, const float* __restrict__ conv_b,
    const float* w0, const float* b0, const float* w1, const float* b1,
    const float* w2, const float* b2, const float* w3, const float* b3,
    const float* w4, const float* b4, const float* w5, const float* b5)
{
    int r = blockIdx.x;            // 0..1023  (output row of Wc)
    int c = threadIdx.x;           // 0..319   (input channel = k)
    if (r >= 960) {
        g_wcT[c * 1024 + r] = 0.f;
        if (c == 0) g_bc[r] = 0.f;
        return;
    }
    int g = r / 160, ro = r % 160;
    const float* wg; const float* bg;
    switch (g) {
        case 0: wg = w0; bg = b0; break;
        case 1: wg = w1; bg = b1; break;
        case 2: wg = w2; bg = b2; break;
        case 3: wg = w3; bg = b3; break;
        case 4: wg = w4; bg = b4; break;
        default: wg = w5; bg = b5; break;
    }
    int half = (g >= 3) ? 1 : 0;
    __shared__ float wrow[160];
    if (threadIdx.x < 160) wrow[threadIdx.x] = __ldg(wg + ro * 160 + threadIdx.x);
    __syncthreads();
    const float* cw = conv_w + (size_t)half * 160 * 320 + c;
    float s = 0.f;
#pragma unroll 4
    for (int d = 0; d < 160; d++)
        s += wrow[d] * __ldg(cw + d * 320);
    g_wcT[c * 1024 + r] = s;
    if (c == 0) {
        float sb = __ldg(bg + ro);
        const float* cb = conv_b + half * 160;
        for (int d = 0; d < 160; d++) sb += wrow[d] * __ldg(cb + d);
        g_bc[r] = sb;
    }
}

// ---------------------------------------------------------------------------
// 3) FFMA2 GEMM: qkv[960][131072] = Wc @ LN(x) + bc   (LN fused in B staging)
//    BM=128, BN=128, BK=16, 256 threads, double-buffered smem,
//    warp tile 32m x 64n, thread tile 8m x 8n (32 FFMA2 / k-step / thread).
// ---------------------------------------------------------------------------
__global__ void __launch_bounds__(256, 2) gemm_qkv_kernel(
    const float* __restrict__ x,
    const float* __restrict__ lnw, const float* __restrict__ lnb)
{
    __shared__ float As[2][16][128];    // [stage][k][m]
    __shared__ float Bs[2][16][128];    // [stage][k][n]
    __shared__ float sLnw[320], sLnb[320];

    int tid  = threadIdx.x;
    int wid  = tid >> 5, lane = tid & 31;
    int ly   = lane >> 3;              // 0..3  -> m sub-tile of 8
    int lx   = lane & 7;               // 0..7  -> n sub-tile (2x float4)
    int wm   = (wid & 3) * 32;         // warp m offset
    int wn   = (wid >> 2) * 64;        // warp n offset
    int m0   = blockIdx.x * 128;       // 0..896 (rows >=960 zero-padded)
    int n0   = blockIdx.y * 128;

    // ln params to smem — STRIDED: block has 256 threads, need 320 entries
    // (R10 bug: `if (tid < 320)` left entries 256..319 garbage -> rel_err 0.45)
    for (int i = tid; i < 320; i += 256) {
        sLnw[i] = __ldg(lnw + i);
        sLnb[i] = __ldg(lnb + i);
    }

    int b = n0 >> 16;
    const float* xb = x + (size_t)b * CCH * HWX + (n0 & 65535);
    int tn = tid & 127;                // B column owned by this thread
    int kp = tid >> 7;                 // 0/1 (k parity group)
    float meanv = g_mean[n0 + tn];
    float rstdv = g_rstd[n0 + tn];
    __syncthreads();                   // sLnw/sLnb ready

    float Ar[8], Br[8];
    // ---- global load of chunk k0: A 8 elems, B 8 elems (LN applied) ----
#define LOAD_CHUNK(k0)                                                        \
    do {                                                                      \
        _Pragma("unroll")                                                     \
        for (int i = 0; i < 8; i++) {                                         \
            int kk = i * 2 + kp;                                              \
            Ar[i] = __ldg(&g_wcT[(size_t)((k0) + kk) * 1024 + m0 + tn]);      \
            float v = __ldg(xb + (size_t)((k0) + kk) * HWX + tn);             \
            Br[i] = fmaf((v - meanv) * rstdv, sLnw[(k0) + kk], sLnb[(k0) + kk]); \
        }                                                                     \
    } while (0)
#define STORE_CHUNK(st)                                                       \
    do {                                                                      \
        _Pragma("unroll")                                                     \
        for (int i = 0; i < 8; i++) {                                         \
            int kk = i * 2 + kp;                                              \
            As[st][kk][tn] = Ar[i];                                           \
            Bs[st][kk][tn] = Br[i];                                           \
        }                                                                     \
    } while (0)

    float2 acc[8][4];
#pragma unroll
    for (int i = 0; i < 8; i++)
#pragma unroll
        for (int j = 0; j < 4; j++) acc[i][j] = make_float2(0.f, 0.f);

    LOAD_CHUNK(0);
    STORE_CHUNK(0);
    __syncthreads();

    for (int c = 0; c < 20; c++) {
        int cur = c & 1;
        if (c < 19) LOAD_CHUNK((c + 1) * 16);
#pragma unroll
        for (int kk = 0; kk < 16; kk++) {
            float4 a0 = *(const float4*)&As[cur][kk][wm + ly * 8];
            float4 a1 = *(const float4*)&As[cur][kk][wm + ly * 8 + 4];
            float4 b0 = *(const float4*)&Bs[cur][kk][wn + lx * 4];
            float4 b1 = *(const float4*)&Bs[cur][kk][wn + 32 + lx * 4];
            float2 bv0 = make_float2(b0.x, b0.y);
            float2 bv1 = make_float2(b0.z, b0.w);
            float2 bv2 = make_float2(b1.x, b1.y);
            float2 bv3 = make_float2(b1.z, b1.w);
            float a[8] = {a0.x, a0.y, a0.z, a0.w, a1.x, a1.y, a1.z, a1.w};
#pragma unroll
            for (int i = 0; i < 8; i++) {
                float2 av = make_float2(a[i], a[i]);
                acc[i][0] = ffma2(av, bv0, acc[i][0]);
                acc[i][1] = ffma2(av, bv1, acc[i][1]);
                acc[i][2] = ffma2(av, bv2, acc[i][2]);
                acc[i][3] = ffma2(av, bv3, acc[i][3]);
            }
        }
        if (c < 19) {
            STORE_CHUNK(1 - cur);
            __syncthreads();
        }
    }

    // epilogue: row r = m0+wm+ly*8+i ; cols n0+wn+lx*4 (+0..3) and +32
#pragma unroll
    for (int i = 0; i < 8; i++) {
        int r = m0 + wm + ly * 8 + i;
        if (r < 960) {
            float bias = g_bc[r];
            float* op = g_qkv + (size_t)r * NPIX + n0 + wn;
            float4 o0 = make_float4(acc[i][0].x + bias, acc[i][0].y + bias,
                                    acc[i][1].x + bias, acc[i][1].y + bias);
            float4 o1 = make_float4(acc[i][2].x + bias, acc[i][2].y + bias,
                                    acc[i][3].x + bias, acc[i][3].y + bias);
            *(float4*)(op + lx * 4)      = o0;
            *(float4*)(op + 32 + lx * 4) = o1;
        }
    }
#undef LOAD_CHUNK
#undef STORE_CHUNK
}

// ---------------------------------------------------------------------------
// 4) Transpose vertical qkv rows (960 matrices of 256x256) into H-major order
// ---------------------------------------------------------------------------
__global__ void transpose_qkv_kernel() {
    __shared__ float tile[32][33];
    int m = blockIdx.z;
    const float* s = g_qkv + 480ul * NPIX + (size_t)m * HWX;
    float* d       = g_qkvT + (size_t)m * HWX;
    int x0 = blockIdx.x * 32, y0 = blockIdx.y * 32;
    int tx = threadIdx.x, ty = threadIdx.y;
#pragma unroll
    for (int i = 0; i < 4; i++)
        tile[ty + i * 8][tx] = s[(size_t)(y0 + ty + i * 8) * 256 + x0 + tx];
    __syncthreads();
#pragma unroll
    for (int i = 0; i < 4; i++)
        d[(size_t)(x0 + ty + i * 8) * 256 + y0 + tx] = tile[tx][ty + i * 8];
}

// ---------------------------------------------------------------------------
// 5) Axial attention (R6 passing version, unchanged)
// ---------------------------------------------------------------------------
template <int VMODE>
__global__ void __launch_bounds__(256) attn_kernel(float* __restrict__ out)
{
    __shared__ float Ks[128 * 36];
    __shared__ float Vs[128 * 36];
    int hd  = blockIdx.x;
    int seq = blockIdx.y;
    int t   = threadIdx.x;

    const float* qkv = (VMODE == 0) ? g_qkv : g_qkvT;

    const float* qb = qkv + (size_t)(hd * 32) * NPIX + (size_t)seq * 256 + t;
    const float* kb = qkv + (size_t)(160 + hd * 32) * NPIX + (size_t)seq * 256;
    const float* vb = qkv + (size_t)(320 + hd * 32) * NPIX + (size_t)seq * 256;

    float2 q2[16];
#pragma unroll
    for (int c = 0; c < 16; c++) {
        q2[c].x = __ldg(qb + (size_t)(2 * c) * NPIX);
        q2[c].y = __ldg(qb + (size_t)(2 * c + 1) * NPIX);
    }

    float mx = -1e30f, l = 0.f;
    float2 acc[16];
#pragma unroll
    for (int c = 0; c < 16; c++) acc[c] = make_float2(0.f, 0.f);
    const float scale = 0.17677669529663688f;

    for (int chunk = 0; chunk < 2; chunk++) {
        int j0 = chunk * 128;
        __syncthreads();
#pragma unroll
        for (int i = 0; i < 16; i++) {
            int idx = t + i * 256;
            int pos = idx & 127, c = idx >> 7;
            Ks[pos * 36 + c] = __ldg(kb + (size_t)c * NPIX + j0 + pos);
            Vs[pos * 36 + c] = __ldg(vb + (size_t)c * NPIX + j0 + pos);
        }
        __syncthreads();
        for (int j = 0; j < 128; j++) {
            const float4* k4 = (const float4*)(Ks + j * 36);
            const float4* v4 = (const float4*)(Vs + j * 36);
            float2 d2 = make_float2(0.f, 0.f);
#pragma unroll
            for (int c = 0; c < 8; c++) {
                float4 kv = k4[c];
                d2 = ffma2(q2[2 * c],     make_float2(kv.x, kv.y), d2);
                d2 = ffma2(q2[2 * c + 1], make_float2(kv.z, kv.w), d2);
            }
            float s = (d2.x + d2.y) * scale;
            if (s > mx) {
                float corr = __expf(mx - s);
                mx = s; l *= corr;
#pragma unroll
                for (int c = 0; c < 16; c++) { acc[c].x *= corr; acc[c].y *= corr; }
            }
            float p = __expf(s - mx);
            l += p;
            float2 pp = make_float2(p, p);
#pragma unroll
            for (int c = 0; c < 8; c++) {
                float4 vv = v4[c];
                acc[2 * c]     = ffma2(pp, make_float2(vv.x, vv.y), acc[2 * c]);
                acc[2 * c + 1] = ffma2(pp, make_float2(vv.z, vv.w), acc[2 * c + 1]);
            }
        }
    }
    float rl = 1.f / l;
    if (VMODE == 0) {
        int b = seq >> 8, h = seq & 255;
        float* o = out + (size_t)(b * 160 + hd * 32) * HWX + h * 256 + t;
#pragma unroll
        for (int c = 0; c < 16; c++) {
            o[(size_t)(2 * c) * HWX]     = acc[c].x * rl;
            o[(size_t)(2 * c + 1) * HWX] = acc[c].y * rl;
        }
    } else {
        float* o = g_avs + (size_t)(hd * 32) * NPIX + (size_t)seq * 256 + t;
#pragma unroll
        for (int c = 0; c < 16; c++) {
            o[(size_t)(2 * c) * NPIX]     = acc[c].x * rl;
            o[(size_t)(2 * c + 1) * NPIX] = acc[c].y * rl;
        }
    }
}

// ---------------------------------------------------------------------------
// 6) Final transpose of vertical attention output into d_out batches 2..3
// ---------------------------------------------------------------------------
__global__ void transpose_av_kernel(float* __restrict__ outp) {
    __shared__ float tile[32][33];
    int z = blockIdx.z;
    int b = z / 160, c = z % 160;
    const float* s = g_avs + (size_t)(c * 2 + b) * HWX;
    float* d = outp + 2ul * 160ul * HWX + (size_t)z * HWX;
    int x0 = blockIdx.x * 32, y0 = blockIdx.y * 32;
    int tx = threadIdx.x, ty = threadIdx.y;
#pragma unroll
    for (int i = 0; i < 4; i++)
        tile[ty + i * 8][tx] = s[(size_t)(y0 + ty + i * 8) * 256 + x0 + tx];
    __syncthreads();
#pragma unroll
    for (int i = 0; i < 4; i++)
        d[(size_t)(x0 + ty + i * 8) * 256 + y0 + tx] = tile[tx][ty + i * 8];
}

// ---------------------------------------------------------------------------
extern "C" void kernel_launch(void* const* d_in, const int* in_sizes, int n_in,
                              void* d_out, int out_size)
{
    const float* x      = (const float*)d_in[0];
    const float* lnw    = (const float*)d_in[1];
    const float* lnb    = (const float*)d_in[2];
    const float* conv_w = (const float*)d_in[3];
    const float* conv_b = (const float*)d_in[4];
    float* out = (float*)d_out;

    ln_stats_kernel<<<512, 256>>>(x);
    combine_w_kernel<<<1024, 320>>>(conv_w, conv_b,
        (const float*)d_in[5],  (const float*)d_in[6],
        (const float*)d_in[7],  (const float*)d_in[8],
        (const float*)d_in[9],  (const float*)d_in[10],
        (const float*)d_in[11], (const float*)d_in[12],
        (const float*)d_in[13], (const float*)d_in[14],
        (const float*)d_in[15], (const float*)d_in[16]);
    gemm_qkv_kernel<<<dim3(8, 1024), 256>>>(x, lnw, lnb);
    transpose_qkv_kernel<<<dim3(8, 8, 960), dim3(32, 8)>>>();

    attn_kernel<0><<<dim3(5, 512), 256>>>(out);
    attn_kernel<1><<<dim3(5, 512), 256>>>(out);
    transpose_av_kernel<<<dim3(8, 8, 320), dim3(32, 8)>>>(out);
}

// round 12
// speedup vs baseline: 1.7011x; 1.1543x over previous
#include <cuda_runtime.h>
#include <cstdint>

// Problem constants
#define HWX   65536          // 256*256
#define NPIX  131072ul       // 2*256*256
#define CCH   320
#define SPL   160

// Scratch (static __device__ — no allocations allowed)
__device__ float g_mean[131072];
__device__ float g_rstd[131072];
__device__ float g_wcT[320 * 1024];         // combined weights, TRANSPOSED [k][m], cols 960..1023 zero
__device__ float g_bc[1024];                // combined biases (padded, rows>=960 zero)
__device__ float g_qkv[960ul * 131072ul];   // GEMM output: rows 0..479 = h(q,k,v), 480..959 = v(q,k,v)
__device__ float g_qkvT[480ul * 131072ul];  // vertical qkv, H-major
__device__ float g_avs[160ul * 131072ul];   // vertical attn out, [c][b][w][h]

// ---------------------------------------------------------------------------
// packed fp32x2 FMA (sm_103 FFMA2) — 2x fp32 fma throughput
// ---------------------------------------------------------------------------
__device__ __forceinline__ float2 ffma2(float2 a, float2 b, float2 c) {
    float2 d;
    asm("{ .reg .b64 ra, rb, rc, rd;\n\t"
        "mov.b64 ra, {%2, %3}; mov.b64 rb, {%4, %5}; mov.b64 rc, {%6, %7};\n\t"
        "fma.rn.f32x2 rd, ra, rb, rc;\n\t"
        "mov.b64 {%0, %1}, rd; }"
        : "=f"(d.x), "=f"(d.y)
        : "f"(a.x), "f"(a.y), "f"(b.x), "f"(b.y), "f"(c.x), "f"(c.y));
    return d;
}

// ---------------------------------------------------------------------------
// 1) Per-pixel LayerNorm stats over channels
// ---------------------------------------------------------------------------
__global__ void ln_stats_kernel(const float* __restrict__ x) {
    int p  = blockIdx.x * 256 + threadIdx.x;
    int b  = p >> 16;
    int hw = p & 65535;
    const float* xp = x + (size_t)b * CCH * HWX + hw;
    float s = 0.f, s2 = 0.f;
#pragma unroll 4
    for (int c = 0; c < CCH; c++) {
        float v = __ldg(xp + (size_t)c * HWX);
        s += v; s2 += v * v;
    }
    float mu  = s * (1.f / 320.f);
    float var = s2 * (1.f / 320.f) - mu * mu;
    g_mean[p] = mu;
    g_rstd[p] = rsqrtf(var + 1e-5f);
}

// ---------------------------------------------------------------------------
// 2) Fold conv into QKV; store TRANSPOSED fp32 [k][m]. Cols 960..1023 zero.
// ---------------------------------------------------------------------------
__global__ void combine_w_kernel(
    const float* __restrict__ conv_w, const float* __restrict__ conv_b,
    const float* w0, const float* b0, const float* w1, const float* b1,
    const float* w2, const float* b2, const float* w3, const float* b3,
    const float* w4, const float* b4, const float* w5, const float* b5)
{
    int r = blockIdx.x;            // 0..1023  (output row of Wc)
    int c = threadIdx.x;           // 0..319   (input channel = k)
    if (r >= 960) {
        g_wcT[c * 1024 + r] = 0.f;
        if (c == 0) g_bc[r] = 0.f;
        return;
    }
    int g = r / 160, ro = r % 160;
    const float* wg; const float* bg;
    switch (g) {
        case 0: wg = w0; bg = b0; break;
        case 1: wg = w1; bg = b1; break;
        case 2: wg = w2; bg = b2; break;
        case 3: wg = w3; bg = b3; break;
        case 4: wg = w4; bg = b4; break;
        default: wg = w5; bg = b5; break;
    }
    int half = (g >= 3) ? 1 : 0;
    __shared__ float wrow[160];
    if (threadIdx.x < 160) wrow[threadIdx.x] = __ldg(wg + ro * 160 + threadIdx.x);
    __syncthreads();
    const float* cw = conv_w + (size_t)half * 160 * 320 + c;
    float s = 0.f;
#pragma unroll 4
    for (int d = 0; d < 160; d++)
        s += wrow[d] * __ldg(cw + d * 320);
    g_wcT[c * 1024 + r] = s;
    if (c == 0) {
        float sb = __ldg(bg + ro);
        const float* cb = conv_b + half * 160;
        for (int d = 0; d < 160; d++) sb += wrow[d] * __ldg(cb + d);
        g_bc[r] = sb;
    }
}

// ---------------------------------------------------------------------------
// 3) FFMA2 GEMM: qkv[960][131072] = Wc @ LN(x) + bc   (LN fused in B staging)
//    BM=128, BN=128, BK=16, 256 threads, double-buffered smem,
//    warp tile 32m x 64n, thread tile 8m x 8n (32 FFMA2 / k-step / thread).
// ---------------------------------------------------------------------------
__global__ void __launch_bounds__(256, 2) gemm_qkv_kernel(
    const float* __restrict__ x,
    const float* __restrict__ lnw, const float* __restrict__ lnb)
{
    __shared__ float As[2][16][128];    // [stage][k][m]
    __shared__ float Bs[2][16][128];    // [stage][k][n]
    __shared__ float sLnw[320], sLnb[320];

    int tid  = threadIdx.x;
    int wid  = tid >> 5, lane = tid & 31;
    int ly   = lane >> 3;              // 0..3  -> m sub-tile of 8
    int lx   = lane & 7;               // 0..7  -> n sub-tile (2x float4)
    int wm   = (wid & 3) * 32;         // warp m offset
    int wn   = (wid >> 2) * 64;        // warp n offset
    int m0   = blockIdx.x * 128;       // 0..896 (rows >=960 zero-padded)
    int n0   = blockIdx.y * 128;

    // ln params to smem — STRIDED: block has 256 threads, need 320 entries
    for (int i = tid; i < 320; i += 256) {
        sLnw[i] = __ldg(lnw + i);
        sLnb[i] = __ldg(lnb + i);
    }

    int b = n0 >> 16;
    const float* xb = x + (size_t)b * CCH * HWX + (n0 & 65535);
    int tn = tid & 127;                // B column owned by this thread
    int kp = tid >> 7;                 // 0/1 (k parity group)
    float meanv = g_mean[n0 + tn];
    float rstdv = g_rstd[n0 + tn];
    __syncthreads();                   // sLnw/sLnb ready

    float Ar[8], Br[8];
#define LOAD_CHUNK(k0)                                                        \
    do {                                                                      \
        _Pragma("unroll")                                                     \
        for (int i = 0; i < 8; i++) {                                         \
            int kk = i * 2 + kp;                                              \
            Ar[i] = __ldg(&g_wcT[(size_t)((k0) + kk) * 1024 + m0 + tn]);      \
            float v = __ldg(xb + (size_t)((k0) + kk) * HWX + tn);             \
            Br[i] = fmaf((v - meanv) * rstdv, sLnw[(k0) + kk], sLnb[(k0) + kk]); \
        }                                                                     \
    } while (0)
#define STORE_CHUNK(st)                                                       \
    do {                                                                      \
        _Pragma("unroll")                                                     \
        for (int i = 0; i < 8; i++) {                                         \
            int kk = i * 2 + kp;                                              \
            As[st][kk][tn] = Ar[i];                                           \
            Bs[st][kk][tn] = Br[i];                                           \
        }                                                                     \
    } while (0)

    float2 acc[8][4];
#pragma unroll
    for (int i = 0; i < 8; i++)
#pragma unroll
        for (int j = 0; j < 4; j++) acc[i][j] = make_float2(0.f, 0.f);

    LOAD_CHUNK(0);
    STORE_CHUNK(0);
    __syncthreads();

    for (int c = 0; c < 20; c++) {
        int cur = c & 1;
        if (c < 19) LOAD_CHUNK((c + 1) * 16);
#pragma unroll
        for (int kk = 0; kk < 16; kk++) {
            float4 a0 = *(const float4*)&As[cur][kk][wm + ly * 8];
            float4 a1 = *(const float4*)&As[cur][kk][wm + ly * 8 + 4];
            float4 b0 = *(const float4*)&Bs[cur][kk][wn + lx * 4];
            float4 b1 = *(const float4*)&Bs[cur][kk][wn + 32 + lx * 4];
            float2 bv0 = make_float2(b0.x, b0.y);
            float2 bv1 = make_float2(b0.z, b0.w);
            float2 bv2 = make_float2(b1.x, b1.y);
            float2 bv3 = make_float2(b1.z, b1.w);
            float a[8] = {a0.x, a0.y, a0.z, a0.w, a1.x, a1.y, a1.z, a1.w};
#pragma unroll
            for (int i = 0; i < 8; i++) {
                float2 av = make_float2(a[i], a[i]);
                acc[i][0] = ffma2(av, bv0, acc[i][0]);
                acc[i][1] = ffma2(av, bv1, acc[i][1]);
                acc[i][2] = ffma2(av, bv2, acc[i][2]);
                acc[i][3] = ffma2(av, bv3, acc[i][3]);
            }
        }
        if (c < 19) {
            STORE_CHUNK(1 - cur);
            __syncthreads();
        }
    }

#pragma unroll
    for (int i = 0; i < 8; i++) {
        int r = m0 + wm + ly * 8 + i;
        if (r < 960) {
            float bias = g_bc[r];
            float* op = g_qkv + (size_t)r * NPIX + n0 + wn;
            float4 o0 = make_float4(acc[i][0].x + bias, acc[i][0].y + bias,
                                    acc[i][1].x + bias, acc[i][1].y + bias);
            float4 o1 = make_float4(acc[i][2].x + bias, acc[i][2].y + bias,
                                    acc[i][3].x + bias, acc[i][3].y + bias);
            *(float4*)(op + lx * 4)      = o0;
            *(float4*)(op + 32 + lx * 4) = o1;
        }
    }
#undef LOAD_CHUNK
#undef STORE_CHUNK
}

// ---------------------------------------------------------------------------
// 4) Transpose vertical qkv rows (960 matrices of 256x256) into H-major order
// ---------------------------------------------------------------------------
__global__ void transpose_qkv_kernel() {
    __shared__ float tile[32][33];
    int m = blockIdx.z;
    const float* s = g_qkv + 480ul * NPIX + (size_t)m * HWX;
    float* d       = g_qkvT + (size_t)m * HWX;
    int x0 = blockIdx.x * 32, y0 = blockIdx.y * 32;
    int tx = threadIdx.x, ty = threadIdx.y;
#pragma unroll
    for (int i = 0; i < 4; i++)
        tile[ty + i * 8][tx] = s[(size_t)(y0 + ty + i * 8) * 256 + x0 + tx];
    __syncthreads();
#pragma unroll
    for (int i = 0; i < 4; i++)
        d[(size_t)(x0 + ty + i * 8) * 256 + y0 + tx] = tile[tx][ty + i * 8];
}

// ---------------------------------------------------------------------------
// 5) Axial attention v2: 128 threads/block, 2 queries per thread (t, t+128).
//    The 16 broadcast K/V fragment LDS per key are amortized over 64 FFMA2
//    (vs 32 in v1) -> FFMA2-pipe-bound.
// ---------------------------------------------------------------------------
template <int VMODE>
__global__ void __launch_bounds__(128) attn_kernel(float* __restrict__ out)
{
    __shared__ float Ks[128 * 36];
    __shared__ float Vs[128 * 36];
    int hd  = blockIdx.x;        // 0..4
    int seq = blockIdx.y;        // 0..511
    int t   = threadIdx.x;       // 0..127; queries t and t+128

    const float* qkv = (VMODE == 0) ? g_qkv : g_qkvT;

    const float* qa = qkv + (size_t)(hd * 32) * NPIX + (size_t)seq * 256 + t;
    const float* kb = qkv + (size_t)(160 + hd * 32) * NPIX + (size_t)seq * 256;
    const float* vb = qkv + (size_t)(320 + hd * 32) * NPIX + (size_t)seq * 256;

    float2 q2a[16], q2b[16];
#pragma unroll
    for (int c = 0; c < 16; c++) {
        q2a[c].x = __ldg(qa + (size_t)(2 * c) * NPIX);
        q2a[c].y = __ldg(qa + (size_t)(2 * c + 1) * NPIX);
        q2b[c].x = __ldg(qa + (size_t)(2 * c) * NPIX + 128);
        q2b[c].y = __ldg(qa + (size_t)(2 * c + 1) * NPIX + 128);
    }

    float mxa = -1e30f, la = 0.f;
    float mxb = -1e30f, lb = 0.f;
    float2 acca[16], accb[16];
#pragma unroll
    for (int c = 0; c < 16; c++) { acca[c] = make_float2(0.f, 0.f); accb[c] = make_float2(0.f, 0.f); }
    const float scale = 0.17677669529663688f;   // 1/sqrt(32)

    for (int chunk = 0; chunk < 2; chunk++) {
        int j0 = chunk * 128;
        __syncthreads();
        // staging: thread t owns key position t, loads all 32 channels
#pragma unroll
        for (int i = 0; i < 32; i++) {
            Ks[t * 36 + i] = __ldg(kb + (size_t)i * NPIX + j0 + t);
            Vs[t * 36 + i] = __ldg(vb + (size_t)i * NPIX + j0 + t);
        }
        __syncthreads();
        for (int j = 0; j < 128; j++) {
            const float4* k4 = (const float4*)(Ks + j * 36);
            const float4* v4 = (const float4*)(Vs + j * 36);
            float2 da = make_float2(0.f, 0.f);
            float2 db = make_float2(0.f, 0.f);
#pragma unroll
            for (int c = 0; c < 8; c++) {
                float4 kv = k4[c];
                float2 k01 = make_float2(kv.x, kv.y);
                float2 k23 = make_float2(kv.z, kv.w);
                da = ffma2(q2a[2 * c],     k01, da);
                da = ffma2(q2a[2 * c + 1], k23, da);
                db = ffma2(q2b[2 * c],     k01, db);
                db = ffma2(q2b[2 * c + 1], k23, db);
            }
            float sa = (da.x + da.y) * scale;
            float sb = (db.x + db.y) * scale;
            if (sa > mxa) {                       // rare rescale (online softmax)
                float corr = __expf(mxa - sa);
                mxa = sa; la *= corr;
#pragma unroll
                for (int c = 0; c < 16; c++) { acca[c].x *= corr; acca[c].y *= corr; }
            }
            if (sb > mxb) {
                float corr = __expf(mxb - sb);
                mxb = sb; lb *= corr;
#pragma unroll
                for (int c = 0; c < 16; c++) { accb[c].x *= corr; accb[c].y *= corr; }
            }
            float pa = __expf(sa - mxa);
            float pb = __expf(sb - mxb);
            la += pa; lb += pb;
            float2 ppa = make_float2(pa, pa);
            float2 ppb = make_float2(pb, pb);
#pragma unroll
            for (int c = 0; c < 8; c++) {
                float4 vv = v4[c];
                float2 v01 = make_float2(vv.x, vv.y);
                float2 v23 = make_float2(vv.z, vv.w);
                acca[2 * c]     = ffma2(ppa, v01, acca[2 * c]);
                acca[2 * c + 1] = ffma2(ppa, v23, acca[2 * c + 1]);
                accb[2 * c]     = ffma2(ppb, v01, accb[2 * c]);
                accb[2 * c + 1] = ffma2(ppb, v23, accb[2 * c + 1]);
            }
        }
    }
    float rla = 1.f / la;
    float rlb = 1.f / lb;
    if (VMODE == 0) {
        int b = seq >> 8, h = seq & 255;
        float* o = out + (size_t)(b * 160 + hd * 32) * HWX + h * 256 + t;
#pragma unroll
        for (int c = 0; c < 16; c++) {
            o[(size_t)(2 * c) * HWX]           = acca[c].x * rla;
            o[(size_t)(2 * c + 1) * HWX]       = acca[c].y * rla;
            o[(size_t)(2 * c) * HWX + 128]     = accb[c].x * rlb;
            o[(size_t)(2 * c + 1) * HWX + 128] = accb[c].y * rlb;
        }
    } else {
        float* o = g_avs + (size_t)(hd * 32) * NPIX + (size_t)seq * 256 + t;
#pragma unroll
        for (int c = 0; c < 16; c++) {
            o[(size_t)(2 * c) * NPIX]           = acca[c].x * rla;
            o[(size_t)(2 * c + 1) * NPIX]       = acca[c].y * rla;
            o[(size_t)(2 * c) * NPIX + 128]     = accb[c].x * rlb;
            o[(size_t)(2 * c + 1) * NPIX + 128] = accb[c].y * rlb;
        }
    }
}

// ---------------------------------------------------------------------------
// 6) Final transpose of vertical attention output into d_out batches 2..3
// ---------------------------------------------------------------------------
__global__ void transpose_av_kernel(float* __restrict__ outp) {
    __shared__ float tile[32][33];
    int z = blockIdx.z;
    int b = z / 160, c = z % 160;
    const float* s = g_avs + (size_t)(c * 2 + b) * HWX;
    float* d = outp + 2ul * 160ul * HWX + (size_t)z * HWX;
    int x0 = blockIdx.x * 32, y0 = blockIdx.y * 32;
    int tx = threadIdx.x, ty = threadIdx.y;
#pragma unroll
    for (int i = 0; i < 4; i++)
        tile[ty + i * 8][tx] = s[(size_t)(y0 + ty + i * 8) * 256 + x0 + tx];
    __syncthreads();
#pragma unroll
    for (int i = 0; i < 4; i++)
        d[(size_t)(x0 + ty + i * 8) * 256 + y0 + tx] = tile[tx][ty + i * 8];
}

// ---------------------------------------------------------------------------
extern "C" void kernel_launch(void* const* d_in, const int* in_sizes, int n_in,
                              void* d_out, int out_size)
{
    const float* x      = (const float*)d_in[0];
    const float* lnw    = (const float*)d_in[1];
    const float* lnb    = (const float*)d_in[2];
    const float* conv_w = (const float*)d_in[3];
    const float* conv_b = (const float*)d_in[4];
    float* out = (float*)d_out;

    ln_stats_kernel<<<512, 256>>>(x);
    combine_w_kernel<<<1024, 320>>>(conv_w, conv_b,
        (const float*)d_in[5],  (const float*)d_in[6],
        (const float*)d_in[7],  (const float*)d_in[8],
        (const float*)d_in[9],  (const float*)d_in[10],
        (const float*)d_in[11], (const float*)d_in[12],
        (const float*)d_in[13], (const float*)d_in[14],
        (const float*)d_in[15], (const float*)d_in[16]);
    gemm_qkv_kernel<<<dim3(8, 1024), 256>>>(x, lnw, lnb);
    transpose_qkv_kernel<<<dim3(8, 8, 960), dim3(32, 8)>>>();

    attn_kernel<0><<<dim3(5, 512), 128>>>(out);
    attn_kernel<1><<<dim3(5, 512), 128>>>(out);
    transpose_av_kernel<<<dim3(8, 8, 320), dim3(32, 8)>>>(out);
}

// round 13
// speedup vs baseline: 1.7926x; 1.0538x over previous
#include <cuda_runtime.h>
#include <cstdint>

// Problem constants
#define HWX   65536          // 256*256
#define NPIX  131072ul       // 2*256*256
#define CCH   320
#define SPL   160

// Scratch (static __device__ — no allocations allowed)
__device__ float g_mean[131072];
__device__ float g_rstd[131072];
__device__ float g_wcT[320 * 1024];         // combined weights, TRANSPOSED [k][m], cols 960..1023 zero
__device__ float g_bc[1024];                // combined biases (padded, rows>=960 zero)
__device__ float g_qkv[960ul * 131072ul];   // GEMM output: rows 0..479 = h(q,k,v), 480..959 = v(q,k,v)
__device__ float g_qkvT[480ul * 131072ul];  // vertical qkv, H-major
__device__ float g_avs[160ul * 131072ul];   // vertical attn out, [c][b][w][h]

// ---------------------------------------------------------------------------
// packed fp32x2 FMA (sm_103 FFMA2) — 2x fp32 fma throughput
// ---------------------------------------------------------------------------
__device__ __forceinline__ float2 ffma2(float2 a, float2 b, float2 c) {
    float2 d;
    asm("{ .reg .b64 ra, rb, rc, rd;\n\t"
        "mov.b64 ra, {%2, %3}; mov.b64 rb, {%4, %5}; mov.b64 rc, {%6, %7};\n\t"
        "fma.rn.f32x2 rd, ra, rb, rc;\n\t"
        "mov.b64 {%0, %1}, rd; }"
        : "=f"(d.x), "=f"(d.y)
        : "f"(a.x), "f"(a.y), "f"(b.x), "f"(b.y), "f"(c.x), "f"(c.y));
    return d;
}

// ---------------------------------------------------------------------------
// 1) Per-pixel LayerNorm stats over channels
// ---------------------------------------------------------------------------
__global__ void ln_stats_kernel(const float* __restrict__ x) {
    int p  = blockIdx.x * 256 + threadIdx.x;
    int b  = p >> 16;
    int hw = p & 65535;
    const float* xp = x + (size_t)b * CCH * HWX + hw;
    float s = 0.f, s2 = 0.f;
#pragma unroll 4
    for (int c = 0; c < CCH; c++) {
        float v = __ldg(xp + (size_t)c * HWX);
        s += v; s2 += v * v;
    }
    float mu  = s * (1.f / 320.f);
    float var = s2 * (1.f / 320.f) - mu * mu;
    g_mean[p] = mu;
    g_rstd[p] = rsqrtf(var + 1e-5f);
}

// ---------------------------------------------------------------------------
// 2) Fold conv into QKV; store TRANSPOSED fp32 [k][m]. Cols 960..1023 zero.
// ---------------------------------------------------------------------------
__global__ void combine_w_kernel(
    const float* __restrict__ conv_w, const float* __restrict__ conv_b,
    const float* w0, const float* b0, const float* w1, const float* b1,
    const float* w2, const float* b2, const float* w3, const float* b3,
    const float* w4, const float* b4, const float* w5, const float* b5)
{
    int r = blockIdx.x;            // 0..1023  (output row of Wc)
    int c = threadIdx.x;           // 0..319   (input channel = k)
    if (r >= 960) {
        g_wcT[c * 1024 + r] = 0.f;
        if (c == 0) g_bc[r] = 0.f;
        return;
    }
    int g = r / 160, ro = r % 160;
    const float* wg; const float* bg;
    switch (g) {
        case 0: wg = w0; bg = b0; break;
        case 1: wg = w1; bg = b1; break;
        case 2: wg = w2; bg = b2; break;
        case 3: wg = w3; bg = b3; break;
        case 4: wg = w4; bg = b4; break;
        default: wg = w5; bg = b5; break;
    }
    int half = (g >= 3) ? 1 : 0;
    __shared__ float wrow[160];
    if (threadIdx.x < 160) wrow[threadIdx.x] = __ldg(wg + ro * 160 + threadIdx.x);
    __syncthreads();
    const float* cw = conv_w + (size_t)half * 160 * 320 + c;
    float s = 0.f;
#pragma unroll 4
    for (int d = 0; d < 160; d++)
        s += wrow[d] * __ldg(cw + d * 320);
    g_wcT[c * 1024 + r] = s;
    if (c == 0) {
        float sb = __ldg(bg + ro);
        const float* cb = conv_b + half * 160;
        for (int d = 0; d < 160; d++) sb += wrow[d] * __ldg(cb + d);
        g_bc[r] = sb;
    }
}

// ---------------------------------------------------------------------------
// 3) FFMA2 GEMM: qkv[960][131072] = Wc @ LN(x) + bc   (LN fused in B staging)
//    BM=128, BN=128, BK=16, 256 threads, double-buffered smem,
//    warp tile 32m x 64n, thread tile 8m x 8n (32 FFMA2 / k-step / thread).
//    R13: float4 staging — thread owns quad column qm (m & n) and k rows
//    qk0, qk0+8: 4x LDG.128 + 4x STS.128 per chunk (was 16 LDG.32 + 32 STS.32)
// ---------------------------------------------------------------------------
__global__ void __launch_bounds__(256, 2) gemm_qkv_kernel(
    const float* __restrict__ x,
    const float* __restrict__ lnw, const float* __restrict__ lnb)
{
    __shared__ float As[2][16][128];    // [stage][k][m]
    __shared__ float Bs[2][16][128];    // [stage][k][n]
    __shared__ float sLnw[320], sLnb[320];

    int tid  = threadIdx.x;
    int wid  = tid >> 5, lane = tid & 31;
    int ly   = lane >> 3;              // 0..3  -> m sub-tile of 8
    int lx   = lane & 7;               // 0..7  -> n sub-tile (2x float4)
    int wm   = (wid & 3) * 32;         // warp m offset
    int wn   = (wid >> 2) * 64;        // warp n offset
    int m0   = blockIdx.x * 128;       // 0..896 (rows >=960 zero-padded)
    int n0   = blockIdx.y * 128;

    // staging coords: quad qm (0..31) within row, k rows qk0 and qk0+8
    int qm  = tid & 31;
    int qk0 = tid >> 5;                // 0..7

    // ln params to smem — STRIDED (320 entries, 256 threads)
    for (int i = tid; i < 320; i += 256) {
        sLnw[i] = __ldg(lnw + i);
        sLnb[i] = __ldg(lnb + i);
    }

    int b = n0 >> 16;
    const float* xb = x + (size_t)b * CCH * HWX + (n0 & 65535);
    float4 mean4 = *(const float4*)&g_mean[n0 + qm * 4];
    float4 rstd4 = *(const float4*)&g_rstd[n0 + qm * 4];
    __syncthreads();                   // sLnw/sLnb ready

    float4 Arq[2], Brq[2];
#define LOAD_CHUNK(k0)                                                        \
    do {                                                                      \
        _Pragma("unroll")                                                     \
        for (int i = 0; i < 2; i++) {                                         \
            int k = (k0) + qk0 + i * 8;                                       \
            Arq[i] = *(const float4*)&g_wcT[(size_t)k * 1024 + m0 + qm * 4];  \
            Brq[i] = *(const float4*)&xb[(size_t)k * HWX + qm * 4];          \
        }                                                                     \
    } while (0)
#define STORE_CHUNK(st, k0)                                                   \
    do {                                                                      \
        _Pragma("unroll")                                                     \
        for (int i = 0; i < 2; i++) {                                         \
            int kk = qk0 + i * 8;                                             \
            *(float4*)&As[st][kk][qm * 4] = Arq[i];                           \
            float lw = sLnw[(k0) + kk], lbv = sLnb[(k0) + kk];                \
            float4 v = Brq[i], o;                                             \
            o.x = fmaf((v.x - mean4.x) * rstd4.x, lw, lbv);                   \
            o.y = fmaf((v.y - mean4.y) * rstd4.y, lw, lbv);                   \
            o.z = fmaf((v.z - mean4.z) * rstd4.z, lw, lbv);                   \
            o.w = fmaf((v.w - mean4.w) * rstd4.w, lw, lbv);                   \
            *(float4*)&Bs[st][kk][qm * 4] = o;                                \
        }                                                                     \
    } while (0)

    float2 acc[8][4];
#pragma unroll
    for (int i = 0; i < 8; i++)
#pragma unroll
        for (int j = 0; j < 4; j++) acc[i][j] = make_float2(0.f, 0.f);

    LOAD_CHUNK(0);
    STORE_CHUNK(0, 0);
    __syncthreads();

    for (int c = 0; c < 20; c++) {
        int cur = c & 1;
        if (c < 19) LOAD_CHUNK((c + 1) * 16);
#pragma unroll
        for (int kk = 0; kk < 16; kk++) {
            float4 a0 = *(const float4*)&As[cur][kk][wm + ly * 8];
            float4 a1 = *(const float4*)&As[cur][kk][wm + ly * 8 + 4];
            float4 b0 = *(const float4*)&Bs[cur][kk][wn + lx * 4];
            float4 b1 = *(const float4*)&Bs[cur][kk][wn + 32 + lx * 4];
            float2 bv0 = make_float2(b0.x, b0.y);
            float2 bv1 = make_float2(b0.z, b0.w);
            float2 bv2 = make_float2(b1.x, b1.y);
            float2 bv3 = make_float2(b1.z, b1.w);
            float a[8] = {a0.x, a0.y, a0.z, a0.w, a1.x, a1.y, a1.z, a1.w};
#pragma unroll
            for (int i = 0; i < 8; i++) {
                float2 av = make_float2(a[i], a[i]);
                acc[i][0] = ffma2(av, bv0, acc[i][0]);
                acc[i][1] = ffma2(av, bv1, acc[i][1]);
                acc[i][2] = ffma2(av, bv2, acc[i][2]);
                acc[i][3] = ffma2(av, bv3, acc[i][3]);
            }
        }
        if (c < 19) {
            STORE_CHUNK(1 - cur, (c + 1) * 16);
            __syncthreads();
        }
    }

#pragma unroll
    for (int i = 0; i < 8; i++) {
        int r = m0 + wm + ly * 8 + i;
        if (r < 960) {
            float bias = g_bc[r];
            float* op = g_qkv + (size_t)r * NPIX + n0 + wn;
            float4 o0 = make_float4(acc[i][0].x + bias, acc[i][0].y + bias,
                                    acc[i][1].x + bias, acc[i][1].y + bias);
            float4 o1 = make_float4(acc[i][2].x + bias, acc[i][2].y + bias,
                                    acc[i][3].x + bias, acc[i][3].y + bias);
            *(float4*)(op + lx * 4)      = o0;
            *(float4*)(op + 32 + lx * 4) = o1;
        }
    }
#undef LOAD_CHUNK
#undef STORE_CHUNK
}

// ---------------------------------------------------------------------------
// 4) Transpose vertical qkv rows (960 matrices of 256x256) into H-major order
// ---------------------------------------------------------------------------
__global__ void transpose_qkv_kernel() {
    __shared__ float tile[32][33];
    int m = blockIdx.z;
    const float* s = g_qkv + 480ul * NPIX + (size_t)m * HWX;
    float* d       = g_qkvT + (size_t)m * HWX;
    int x0 = blockIdx.x * 32, y0 = blockIdx.y * 32;
    int tx = threadIdx.x, ty = threadIdx.y;
#pragma unroll
    for (int i = 0; i < 4; i++)
        tile[ty + i * 8][tx] = s[(size_t)(y0 + ty + i * 8) * 256 + x0 + tx];
    __syncthreads();
#pragma unroll
    for (int i = 0; i < 4; i++)
        d[(size_t)(x0 + ty + i * 8) * 256 + y0 + tx] = tile[tx][ty + i * 8];
}

// ---------------------------------------------------------------------------
// 5) Axial attention v2: 128 threads/block, 2 queries per thread (t, t+128).
// ---------------------------------------------------------------------------
template <int VMODE>
__global__ void __launch_bounds__(128) attn_kernel(float* __restrict__ out)
{
    __shared__ float Ks[128 * 36];
    __shared__ float Vs[128 * 36];
    int hd  = blockIdx.x;        // 0..4
    int seq = blockIdx.y;        // 0..511
    int t   = threadIdx.x;       // 0..127; queries t and t+128

    const float* qkv = (VMODE == 0) ? g_qkv : g_qkvT;

    const float* qa = qkv + (size_t)(hd * 32) * NPIX + (size_t)seq * 256 + t;
    const float* kb = qkv + (size_t)(160 + hd * 32) * NPIX + (size_t)seq * 256;
    const float* vb = qkv + (size_t)(320 + hd * 32) * NPIX + (size_t)seq * 256;

    float2 q2a[16], q2b[16];
#pragma unroll
    for (int c = 0; c < 16; c++) {
        q2a[c].x = __ldg(qa + (size_t)(2 * c) * NPIX);
        q2a[c].y = __ldg(qa + (size_t)(2 * c + 1) * NPIX);
        q2b[c].x = __ldg(qa + (size_t)(2 * c) * NPIX + 128);
        q2b[c].y = __ldg(qa + (size_t)(2 * c + 1) * NPIX + 128);
    }

    float mxa = -1e30f, la = 0.f;
    float mxb = -1e30f, lb = 0.f;
    float2 acca[16], accb[16];
#pragma unroll
    for (int c = 0; c < 16; c++) { acca[c] = make_float2(0.f, 0.f); accb[c] = make_float2(0.f, 0.f); }
    const float scale = 0.17677669529663688f;   // 1/sqrt(32)

    for (int chunk = 0; chunk < 2; chunk++) {
        int j0 = chunk * 128;
        __syncthreads();
#pragma unroll
        for (int i = 0; i < 32; i++) {
            Ks[t * 36 + i] = __ldg(kb + (size_t)i * NPIX + j0 + t);
            Vs[t * 36 + i] = __ldg(vb + (size_t)i * NPIX + j0 + t);
        }
        __syncthreads();
        for (int j = 0; j < 128; j++) {
            const float4* k4 = (const float4*)(Ks + j * 36);
            const float4* v4 = (const float4*)(Vs + j * 36);
            float2 da = make_float2(0.f, 0.f);
            float2 db = make_float2(0.f, 0.f);
#pragma unroll
            for (int c = 0; c < 8; c++) {
                float4 kv = k4[c];
                float2 k01 = make_float2(kv.x, kv.y);
                float2 k23 = make_float2(kv.z, kv.w);
                da = ffma2(q2a[2 * c],     k01, da);
                da = ffma2(q2a[2 * c + 1], k23, da);
                db = ffma2(q2b[2 * c],     k01, db);
                db = ffma2(q2b[2 * c + 1], k23, db);
            }
            float sa = (da.x + da.y) * scale;
            float sb = (db.x + db.y) * scale;
            if (sa > mxa) {
                float corr = __expf(mxa - sa);
                mxa = sa; la *= corr;
#pragma unroll
                for (int c = 0; c < 16; c++) { acca[c].x *= corr; acca[c].y *= corr; }
            }
            if (sb > mxb) {
                float corr = __expf(mxb - sb);
                mxb = sb; lb *= corr;
#pragma unroll
                for (int c = 0; c < 16; c++) { accb[c].x *= corr; accb[c].y *= corr; }
            }
            float pa = __expf(sa - mxa);
            float pb = __expf(sb - mxb);
            la += pa; lb += pb;
            float2 ppa = make_float2(pa, pa);
            float2 ppb = make_float2(pb, pb);
#pragma unroll
            for (int c = 0; c < 8; c++) {
                float4 vv = v4[c];
                float2 v01 = make_float2(vv.x, vv.y);
                float2 v23 = make_float2(vv.z, vv.w);
                acca[2 * c]     = ffma2(ppa, v01, acca[2 * c]);
                acca[2 * c + 1] = ffma2(ppa, v23, acca[2 * c + 1]);
                accb[2 * c]     = ffma2(ppb, v01, accb[2 * c]);
                accb[2 * c + 1] = ffma2(ppb, v23, accb[2 * c + 1]);
            }
        }
    }
    float rla = 1.f / la;
    float rlb = 1.f / lb;
    if (VMODE == 0) {
        int b = seq >> 8, h = seq & 255;
        float* o = out + (size_t)(b * 160 + hd * 32) * HWX + h * 256 + t;
#pragma unroll
        for (int c = 0; c < 16; c++) {
            o[(size_t)(2 * c) * HWX]           = acca[c].x * rla;
            o[(size_t)(2 * c + 1) * HWX]       = acca[c].y * rla;
            o[(size_t)(2 * c) * HWX + 128]     = accb[c].x * rlb;
            o[(size_t)(2 * c + 1) * HWX + 128] = accb[c].y * rlb;
        }
    } else {
        float* o = g_avs + (size_t)(hd * 32) * NPIX + (size_t)seq * 256 + t;
#pragma unroll
        for (int c = 0; c < 16; c++) {
            o[(size_t)(2 * c) * NPIX]           = acca[c].x * rla;
            o[(size_t)(2 * c + 1) * NPIX]       = acca[c].y * rla;
            o[(size_t)(2 * c) * NPIX + 128]     = accb[c].x * rlb;
            o[(size_t)(2 * c + 1) * NPIX + 128] = accb[c].y * rlb;
        }
    }
}

// ---------------------------------------------------------------------------
// 6) Final transpose of vertical attention output into d_out batches 2..3
// ---------------------------------------------------------------------------
__global__ void transpose_av_kernel(float* __restrict__ outp) {
    __shared__ float tile[32][33];
    int z = blockIdx.z;
    int b = z / 160, c = z % 160;
    const float* s = g_avs + (size_t)(c * 2 + b) * HWX;
    float* d = outp + 2ul * 160ul * HWX + (size_t)z * HWX;
    int x0 = blockIdx.x * 32, y0 = blockIdx.y * 32;
    int tx = threadIdx.x, ty = threadIdx.y;
#pragma unroll
    for (int i = 0; i < 4; i++)
        tile[ty + i * 8][tx] = s[(size_t)(y0 + ty + i * 8) * 256 + x0 + tx];
    __syncthreads();
#pragma unroll
    for (int i = 0; i < 4; i++)
        d[(size_t)(x0 + ty + i * 8) * 256 + y0 + tx] = tile[tx][ty + i * 8];
}

// ---------------------------------------------------------------------------
extern "C" void kernel_launch(void* const* d_in, const int* in_sizes, int n_in,
                              void* d_out, int out_size)
{
    const float* x      = (const float*)d_in[0];
    const float* lnw    = (const float*)d_in[1];
    const float* lnb    = (const float*)d_in[2];
    const float* conv_w = (const float*)d_in[3];
    const float* conv_b = (const float*)d_in[4];
    float* out = (float*)d_out;

    ln_stats_kernel<<<512, 256>>>(x);
    combine_w_kernel<<<1024, 320>>>(conv_w, conv_b,
        (const float*)d_in[5],  (const float*)d_in[6],
        (const float*)d_in[7],  (const float*)d_in[8],
        (const float*)d_in[9],  (const float*)d_in[10],
        (const float*)d_in[11], (const float*)d_in[12],
        (const float*)d_in[13], (const float*)d_in[14],
        (const float*)d_in[15], (const float*)d_in[16]);
    gemm_qkv_kernel<<<dim3(8, 1024), 256>>>(x, lnw, lnb);
    transpose_qkv_kernel<<<dim3(8, 8, 960), dim3(32, 8)>>>();

    attn_kernel<0><<<dim3(5, 512), 128>>>(out);
    attn_kernel<1><<<dim3(5, 512), 128>>>(out);
    transpose_av_kernel<<<dim3(8, 8, 320), dim3(32, 8)>>>(out);
}